// round 9
// baseline (speedup 1.0000x reference)
#include <cuda_runtime.h>

#define BATCH 512
#define TLEN 16385
#define NN 16384
#define THREADS 256
#define HALF 8192
#define EPT 32
#define NWARP 8
#define PADL(j) ((j) + (((j) >> 5) << 2))      // pad 4 per 32 -> float4-friendly
#define SMEM_FLOATS (PADL(HALF) + 1)           // 9216 + 1 = 9217 (36.9KB)

__device__ float g_tot[BATCH];                 // u-offset at start of half 1

__device__ __forceinline__ float fsqrt_a(float v) {
    float r; asm("sqrt.approx.f32 %0, %1;" : "=f"(r) : "f"(v)); return r;
}
__device__ __forceinline__ float fex2_a(float v) {
    float r; asm("ex2.approx.f32 %0, %1;" : "=f"(r) : "f"(v)); return r;
}
__device__ __forceinline__ float flg2_a(float v) {
    float r; asm("lg2.approx.f32 %0, %1;" : "=f"(r) : "f"(v)); return r;
}

__device__ __forceinline__ float warp_iscan(float v, unsigned lane) {
    #pragma unroll
    for (int d = 1; d < 32; d <<= 1) {
        float n = __shfl_up_sync(0xffffffffu, v, d);
        if (lane >= d) v += n;
    }
    return v;
}

// coalesced scalar stage of one half-row (+1 boundary elem) into padded smem
__device__ __forceinline__ void stage_half(float* xs, const float* __restrict__ xh,
                                           int tid) {
    #pragma unroll
    for (int k = 0; k < EPT; k++) {
        int j = k * THREADS + tid;
        xs[PADL(j)] = xh[j];
    }
    if (tid == 0) xs[PADL(HALF)] = xh[HALF];
}

// per-thread chunk: plain sum (4 chains) + first elem; tot = T + 0.5*(xlast-f0)
__device__ __forceinline__ void chunk_tot(const float4* __restrict__ xt4,
                                          const float* xs, int blast,
                                          float& f0, float& tot) {
    float4 v0 = xt4[0];
    f0 = v0.x;
    float t0 = v0.x, t1 = v0.y, t2 = v0.z, t3 = v0.w;
    #pragma unroll
    for (int g = 1; g < 8; g++) {
        float4 v = xt4[g];
        t0 += v.x; t1 += v.y; t2 += v.z; t3 += v.w;
    }
    tot = ((t0 + t1) + (t2 + t3)) + 0.5f * (xs[blast] - f0);
}

// ======================= KA: reductions + rank-1 solve =======================
__global__ __launch_bounds__(THREADS, 4)
void vp_reduce(const float* __restrict__ x, const float* __restrict__ params,
               float* __restrict__ o_coeffs, float* __restrict__ o_r2)
{
    extern __shared__ __align__(16) float xs[];
    __shared__ float warp_tot[NWARP];
    __shared__ float warp_scan[NWARP];
    __shared__ float red[NWARP * 6];

    const int tid  = threadIdx.x;
    const int lane = tid & 31;
    const int wid  = tid >> 5;
    const int b    = blockIdx.x;
    const float* __restrict__ xr = x + (size_t)b * TLEN;
    const float r  = params[0];
    const float ny = params[1];
    const bool rhalf = (r == 0.5f);

    const float4* __restrict__ xt4 = (const float4*)(xs + 36 * tid);
    const int blast = 36 * tid + 36;

    float uoff = ny;
    float sA = 0.f, sB = 0.f, sC = 0.f, sD0 = 0.f, sD1 = 0.f, sE = 0.f;

    #pragma unroll 1
    for (int h = 0; h < 2; h++) {
        stage_half(xs, xr + h * HALF, tid);
        __syncthreads();

        float f0, tot;
        chunk_tot(xt4, xs, blast, f0, tot);

        float incw = warp_iscan(tot, lane);
        if (lane == 31) warp_tot[wid] = incw;
        __syncthreads();
        if (wid == 0) {
            // all 32 lanes run the full-mask shfl scan (lanes >= NWARP add 0)
            float v = (lane < NWARP) ? warp_tot[lane] : 0.f;
            v = warp_iscan(v, lane);
            if (lane < NWARP) warp_scan[lane] = v;
        }
        __syncthreads();
        const float bs = uoff + (incw - tot) + (wid ? warp_scan[wid - 1] : 0.f);
        const float b2 = bs + 0.5f * f0;     // u_k = b2 + ps_k - 0.5*xc_k

        float ps = 0.f;
        float4 cur = xt4[0];
        #pragma unroll
        for (int g = 0; g < 8; g++) {
            float4 nxt;
            if (g < 7) nxt = xt4[g + 1];
            else { nxt.x = xs[blast]; nxt.y = nxt.z = nxt.w = 0.f; }
            float e[4] = {cur.y, cur.z, cur.w, nxt.x};
            #pragma unroll
            for (int m = 0; m < 4; m++) {
                float xc = e[m];
                ps += xc;
                float u  = fmaf(-0.5f, xc, b2 + ps);
                float su = rhalf ? fsqrt_a(u) : fex2_a(r * flg2_a(u));
                sA  = fmaf(u, u, sA);
                sB  = fmaf(u, su, sB);
                sC += u;
                sD0 = fmaf(xc, u, sD0);
                sD1 = fmaf(xc, su, sD1);
                sE  = fmaf(xc, xc, sE);
            }
            cur = nxt;
        }
        uoff += warp_scan[NWARP - 1];        // add half total
        if (h == 0 && tid == 0) g_tot[b] = uoff;   // base for half 1 (KB)
        __syncthreads();                     // reads done before restage
    }

    #pragma unroll
    for (int d = 16; d; d >>= 1) {
        sA  += __shfl_xor_sync(~0u, sA,  d);
        sB  += __shfl_xor_sync(~0u, sB,  d);
        sC  += __shfl_xor_sync(~0u, sC,  d);
        sD0 += __shfl_xor_sync(~0u, sD0, d);
        sD1 += __shfl_xor_sync(~0u, sD1, d);
        sE  += __shfl_xor_sync(~0u, sE,  d);
    }
    if (lane == 0) {
        red[wid * 6 + 0] = sA;  red[wid * 6 + 1] = sB;
        red[wid * 6 + 2] = sC;  red[wid * 6 + 3] = sD0;
        red[wid * 6 + 4] = sD1; red[wid * 6 + 5] = sE;
    }
    __syncthreads();
    if (tid == 0) {
        double A = 0, Bb = 0, C = 0, D0 = 0, D1 = 0, E = 0;
        for (int w = 0; w < NWARP; w++) {
            A  += red[w * 6 + 0]; Bb += red[w * 6 + 1];
            C  += red[w * 6 + 2]; D0 += red[w * 6 + 3];
            D1 += red[w * 6 + 4]; E  += red[w * 6 + 5];
        }
        // JAX pinv rcond = 10*max(M,N)*eps truncates sigma_2 -> rank-1 solve
        double hh  = 0.5 * (A - C);
        double s   = sqrt(hh * hh + Bb * Bb);
        double lam = 0.5 * (A + C) + s;          // lambda_1 of Gram
        double w0  = Bb;
        double w1  = Bb * Bb / (hh + s);         // = lam - A, stable form
        double n2  = w0 * w0 + w1 * w1;
        double beta = (w0 * D0 + w1 * D1) / (lam * n2);
        double c0d = beta * w0, c1d = beta * w1;
        o_coeffs[b * 2 + 0] = (float)c0d;
        o_coeffs[b * 2 + 1] = (float)c1d;
        // analytic r2 = E - 2 c.d + c^T G c  (G = [[A,Bb],[Bb,C]])
        double r2 = E - 2.0 * (c0d * D0 + c1d * D1)
                  + (c0d * c0d * A + 2.0 * c0d * c1d * Bb + c1d * c1d * C);
        o_r2[b] = (float)r2;
    }
}

// ======================= KB: outputs, one CTA per half-row ===================
__global__ __launch_bounds__(THREADS, 6)
void vp_output(const float* __restrict__ x, const float* __restrict__ params,
               const float* __restrict__ o_coeffs,
               float* __restrict__ o_xhat, float* __restrict__ o_res)
{
    extern __shared__ __align__(16) float xs[];
    __shared__ float warp_tot[NWARP];
    __shared__ float warp_scan[NWARP];

    const int tid  = threadIdx.x;
    const int lane = tid & 31;
    const int wid  = tid >> 5;
    const int b    = blockIdx.x >> 1;
    const int h    = blockIdx.x & 1;
    const float* __restrict__ xr = x + (size_t)b * TLEN + h * HALF;
    const float r  = params[0];
    const bool rhalf = (r == 0.5f);

    stage_half(xs, xr, tid);
    __syncthreads();

    const float4* __restrict__ xt4 = (const float4*)(xs + 36 * tid);
    const int blast = 36 * tid + 36;

    float f0, tot;
    chunk_tot(xt4, xs, blast, f0, tot);

    float incw = warp_iscan(tot, lane);
    if (lane == 31) warp_tot[wid] = incw;
    __syncthreads();
    if (wid == 0) {
        float v = (lane < NWARP) ? warp_tot[lane] : 0.f;
        v = warp_iscan(v, lane);
        if (lane < NWARP) warp_scan[lane] = v;
    }
    __syncthreads();

    const float uoff = h ? g_tot[b] : params[1];
    const float bs = uoff + (incw - tot) + (wid ? warp_scan[wid - 1] : 0.f);
    const float b2 = bs + 0.5f * f0;
    const float c0 = o_coeffs[b * 2 + 0];
    const float c1 = o_coeffs[b * 2 + 1];

    float4* __restrict__ xh4 = (float4*)(o_xhat + (size_t)b * NN);
    float4* __restrict__ rs4 = (float4*)(o_res  + (size_t)b * NN);
    const int o4 = h * (HALF / 4) + tid * (EPT / 4);

    float ps = 0.f;
    float4 cur = xt4[0];
    #pragma unroll
    for (int g = 0; g < 8; g++) {
        float4 nxt;
        if (g < 7) nxt = xt4[g + 1];
        else { nxt.x = xs[blast]; nxt.y = nxt.z = nxt.w = 0.f; }
        float e[4] = {cur.y, cur.z, cur.w, nxt.x};
        float hv[4], rv[4];
        #pragma unroll
        for (int m = 0; m < 4; m++) {
            float xc = e[m];
            ps += xc;
            float u  = fmaf(-0.5f, xc, b2 + ps);
            float su = rhalf ? fsqrt_a(u) : fex2_a(r * flg2_a(u));
            float xv = fmaf(c0, u, c1 * su);
            hv[m] = xv; rv[m] = xc - xv;
        }
        xh4[o4 + g] = make_float4(hv[0], hv[1], hv[2], hv[3]);
        rs4[o4 + g] = make_float4(rv[0], rv[1], rv[2], rv[3]);
        cur = nxt;
    }
}

extern "C" void kernel_launch(void* const* d_in, const int* in_sizes, int n_in,
                              void* d_out, int out_size)
{
    const float* x      = (const float*)d_in[0];
    const float* params = (const float*)d_in[1];
    if (n_in >= 2 && in_sizes[0] == 2) {       // defensive: metadata order swap
        x      = (const float*)d_in[1];
        params = (const float*)d_in[0];
    }
    float* out      = (float*)d_out;
    float* o_coeffs = out;                                   // 512*1*2
    float* o_xhat   = out + (size_t)BATCH * 2;               // 512*1*16384
    float* o_res    = o_xhat + (size_t)BATCH * NN;           // 512*1*16384
    float* o_r2     = o_res  + (size_t)BATCH * NN;           // 512*1

    size_t smem = SMEM_FLOATS * sizeof(float);
    cudaFuncSetAttribute(vp_reduce, cudaFuncAttributeMaxDynamicSharedMemorySize,
                         (int)smem);
    cudaFuncSetAttribute(vp_output, cudaFuncAttributeMaxDynamicSharedMemorySize,
                         (int)smem);
    vp_reduce<<<BATCH, THREADS, smem>>>(x, params, o_coeffs, o_r2);
    vp_output<<<BATCH * 2, THREADS, smem>>>(x, params, o_coeffs, o_xhat, o_res);
}

// round 11
// speedup vs baseline: 1.7152x; 1.7152x over previous
#include <cuda_runtime.h>

#define BATCH 512
#define TLEN 16385
#define NN 16384
#define THREADS 256
#define HALF 8192
#define EPT 32
#define NWARP 8
#define PADL(j) ((j) + (((j) >> 5) << 2))      // pad 4 per 32 -> float4-friendly
#define XS_WORDS 9220                          // PADL(8192)+1=9217, pad to 16B
#define CHK 2048                               // one checkpoint per 4-elem group
#define SMEM_TOT (XS_WORDS + 2 * CHK)          // 13316 floats = 53.3KB

__device__ __forceinline__ float fsqrt_a(float v) {
    float r; asm("sqrt.approx.f32 %0, %1;" : "=f"(r) : "f"(v)); return r;
}
__device__ __forceinline__ float fex2_a(float v) {
    float r; asm("ex2.approx.f32 %0, %1;" : "=f"(r) : "f"(v)); return r;
}
__device__ __forceinline__ float flg2_a(float v) {
    float r; asm("lg2.approx.f32 %0, %1;" : "=f"(r) : "f"(v)); return r;
}

__device__ __forceinline__ float warp_iscan(float v, unsigned lane) {
    #pragma unroll
    for (int d = 1; d < 32; d <<= 1) {
        float n = __shfl_up_sync(0xffffffffu, v, d);
        if (lane >= d) v += n;
    }
    return v;
}

// coalesced scalar stage of one half-row (+1 boundary elem) into padded smem
__device__ __forceinline__ void stage_half(float* xs, const float* __restrict__ xh,
                                           int tid) {
    #pragma unroll
    for (int k = 0; k < EPT; k++) {
        int j = k * THREADS + tid;
        xs[PADL(j)] = xh[j];
    }
    if (tid == 0) xs[PADL(HALF)] = xh[HALF];
}

__global__ __launch_bounds__(THREADS, 4)
void vp_kernel(const float* __restrict__ x, const float* __restrict__ params,
               float* __restrict__ o_coeffs, float* __restrict__ o_xhat,
               float* __restrict__ o_res, float* __restrict__ o_r2)
{
    extern __shared__ __align__(16) float smem[];
    float* xs   = smem;                       // staged half row (padded)
    float* chk0 = smem + XS_WORDS;            // group-base checkpoints, half 0
    float* chk1 = chk0 + CHK;                 // half 1
    __shared__ float warp_tot[NWARP];
    __shared__ float warp_scan[NWARP];
    __shared__ float red[NWARP * 6];
    __shared__ float cbc[2];

    const int tid  = threadIdx.x;
    const int lane = tid & 31;
    const int wid  = tid >> 5;
    const int b    = blockIdx.x;
    const float* __restrict__ xr = x + (size_t)b * TLEN;
    const float r  = params[0];
    const float ny = params[1];
    const bool rhalf = (r == 0.5f);

    // blocked view for reduction: thread owns x[32t..32t+32]
    const float4* __restrict__ xt4 = (const float4*)(xs + 36 * tid);
    const int blast = 36 * tid + 36;

    float uoff = ny;
    float sA = 0.f, sB = 0.f, sC = 0.f, sD0 = 0.f, sD1 = 0.f, sE = 0.f;

    // ================= Reduction passes over both halves =================
    #pragma unroll 1
    for (int h = 0; h < 2; h++) {
        stage_half(xs, xr + h * HALF, tid);
        __syncthreads();

        // per-thread trapezoid total (4 chains): tot = T + 0.5*(xlast - f0)
        float f0, tot;
        {
            float4 v0 = xt4[0];
            f0 = v0.x;
            float t0 = v0.x, t1 = v0.y, t2 = v0.z, t3 = v0.w;
            #pragma unroll
            for (int g = 1; g < 8; g++) {
                float4 v = xt4[g];
                t0 += v.x; t1 += v.y; t2 += v.z; t3 += v.w;
            }
            tot = ((t0 + t1) + (t2 + t3)) + 0.5f * (xs[blast] - f0);
        }
        float incw = warp_iscan(tot, lane);
        if (lane == 31) warp_tot[wid] = incw;
        __syncthreads();
        if (wid == 0) {
            // all 32 lanes run the full-mask shfl scan (lanes >= NWARP add 0)
            float v = (lane < NWARP) ? warp_tot[lane] : 0.f;
            v = warp_iscan(v, lane);
            if (lane < NWARP) warp_scan[lane] = v;
        }
        __syncthreads();
        const float bs = uoff + (incw - tot) + (wid ? warp_scan[wid - 1] : 0.f);
        const float b2 = bs + 0.5f * f0;     // u_k = b2 + ps_k - 0.5*xc_k
        float* chkh = h ? chk1 : chk0;

        // streaming sums + checkpoint per 4-elem group, indexed by GLOBAL
        // group id (8*tid+g) so the coalesced reader uses chk[f] directly.
        float ps = 0.f;
        float4 cur = xt4[0];
        #pragma unroll
        for (int g = 0; g < 8; g++) {
            chkh[8 * tid + g] = b2 + ps;
            float4 nxt;
            if (g < 7) nxt = xt4[g + 1];
            else { nxt.x = xs[blast]; nxt.y = nxt.z = nxt.w = 0.f; }
            float e[4] = {cur.y, cur.z, cur.w, nxt.x};
            #pragma unroll
            for (int m = 0; m < 4; m++) {
                float xc = e[m];
                ps += xc;
                float u  = fmaf(-0.5f, xc, b2 + ps);
                float su = rhalf ? fsqrt_a(u) : fex2_a(r * flg2_a(u));
                sA  = fmaf(u, u, sA);
                sB  = fmaf(u, su, sB);
                sC += u;
                sD0 = fmaf(xc, u, sD0);
                sD1 = fmaf(xc, su, sD1);
                sE  = fmaf(xc, xc, sE);
            }
            cur = nxt;
        }
        uoff += warp_scan[NWARP - 1];        // half total
        __syncthreads();                     // smem reads done before restage
    }

    // ================= Block reduce + rank-1 pinv solve =================
    #pragma unroll
    for (int d = 16; d; d >>= 1) {
        sA  += __shfl_xor_sync(~0u, sA,  d);
        sB  += __shfl_xor_sync(~0u, sB,  d);
        sC  += __shfl_xor_sync(~0u, sC,  d);
        sD0 += __shfl_xor_sync(~0u, sD0, d);
        sD1 += __shfl_xor_sync(~0u, sD1, d);
        sE  += __shfl_xor_sync(~0u, sE,  d);
    }
    if (lane == 0) {
        red[wid * 6 + 0] = sA;  red[wid * 6 + 1] = sB;
        red[wid * 6 + 2] = sC;  red[wid * 6 + 3] = sD0;
        red[wid * 6 + 4] = sD1; red[wid * 6 + 5] = sE;
    }
    __syncthreads();
    if (tid == 0) {
        double A = 0, Bb = 0, C = 0, D0 = 0, D1 = 0, E = 0;
        for (int w = 0; w < NWARP; w++) {
            A  += red[w * 6 + 0]; Bb += red[w * 6 + 1];
            C  += red[w * 6 + 2]; D0 += red[w * 6 + 3];
            D1 += red[w * 6 + 4]; E  += red[w * 6 + 5];
        }
        // JAX pinv rcond = 10*max(M,N)*eps truncates sigma_2 -> rank-1 solve
        double hh  = 0.5 * (A - C);
        double s   = sqrt(hh * hh + Bb * Bb);
        double lam = 0.5 * (A + C) + s;          // lambda_1 of Gram
        double w0  = Bb;
        double w1  = Bb * Bb / (hh + s);         // = lam - A, stable form
        double n2  = w0 * w0 + w1 * w1;
        double beta = (w0 * D0 + w1 * D1) / (lam * n2);
        double c0d = beta * w0, c1d = beta * w1;
        float c0 = (float)c0d, c1 = (float)c1d;
        cbc[0] = c0; cbc[1] = c1;
        o_coeffs[b * 2 + 0] = c0;
        o_coeffs[b * 2 + 1] = c1;
        // analytic r2 = E - 2 c.d + c^T G c  (G = [[A,Bb],[Bb,C]])
        double r2 = E - 2.0 * (c0d * D0 + c1d * D1)
                  + (c0d * c0d * A + 2.0 * c0d * c1d * Bb + c1d * c1d * C);
        o_r2[b] = (float)r2;
    }
    __syncthreads();
    const float c0 = cbc[0];
    const float c1 = cbc[1];

    // ================= Output passes: COALESCED chunks via checkpoints ======
    // Thread handles float4-chunk f = g*256+tid (consecutive lanes ->
    // coalesced LDS.128 / STG.128, 4 line-wavefronts per store vs 32 blocked).
    // u rebuilt from chk[f]. smem holds half 1 -> emit h=1 first, then h=0.
    float4* __restrict__ xh4 = (float4*)(o_xhat + (size_t)b * NN);
    float4* __restrict__ rs4 = (float4*)(o_res  + (size_t)b * NN);
    const float4* __restrict__ xs4 = (const float4*)xs;
    #pragma unroll 1
    for (int p = 0; p < 2; p++) {
        const int h = 1 - p;                 // p=0 -> h=1 (resident), p=1 -> h=0
        if (p == 1) {
            __syncthreads();                 // prior reads done before restage
            stage_half(xs, xr, tid);         // h = 0
            __syncthreads();
        }
        const float* chkh = h ? chk1 : chk0;
        #pragma unroll
        for (int g = 0; g < 8; g++) {
            const int f = g * THREADS + tid;           // float4 idx in half
            float4 v = xs4[f + (f >> 3)];              // padded float4 view
            float nx = __shfl_down_sync(0xffffffffu, v.x, 1);
            if (lane == 31) nx = xs[PADL(4 * f + 4)];  // warp-edge boundary
            float cb = chkh[f];                        // conflict-free LDS
            float e[4] = {v.y, v.z, v.w, nx};
            float hv[4], rv[4];
            float pl = 0.f;
            #pragma unroll
            for (int m = 0; m < 4; m++) {
                float xc = e[m];
                pl += xc;
                float u  = fmaf(-0.5f, xc, cb + pl);
                float su = rhalf ? fsqrt_a(u) : fex2_a(r * flg2_a(u));
                float xv = fmaf(c0, u, c1 * su);
                hv[m] = xv; rv[m] = xc - xv;
            }
            const int o4 = h * (HALF / 4) + f;         // coalesced across warp
            xh4[o4] = make_float4(hv[0], hv[1], hv[2], hv[3]);
            rs4[o4] = make_float4(rv[0], rv[1], rv[2], rv[3]);
        }
    }
}

extern "C" void kernel_launch(void* const* d_in, const int* in_sizes, int n_in,
                              void* d_out, int out_size)
{
    const float* x      = (const float*)d_in[0];
    const float* params = (const float*)d_in[1];
    if (n_in >= 2 && in_sizes[0] == 2) {       // defensive: metadata order swap
        x      = (const float*)d_in[1];
        params = (const float*)d_in[0];
    }
    float* out      = (float*)d_out;
    float* o_coeffs = out;                                   // 512*1*2
    float* o_xhat   = out + (size_t)BATCH * 2;               // 512*1*16384
    float* o_res    = o_xhat + (size_t)BATCH * NN;           // 512*1*16384
    float* o_r2     = o_res  + (size_t)BATCH * NN;           // 512*1

    size_t smem = SMEM_TOT * sizeof(float);
    cudaFuncSetAttribute(vp_kernel, cudaFuncAttributeMaxDynamicSharedMemorySize,
                         (int)smem);
    vp_kernel<<<BATCH, THREADS, smem>>>(x, params, o_coeffs, o_xhat, o_res, o_r2);
}